// round 1
// baseline (speedup 1.0000x reference)
#include <cuda_runtime.h>
#include <math.h>

#define Bn   8
#define Cn   64
#define Hn   128
#define Wn   128
#define Kn   9
#define OMC  27            // 18 offset channels + 9 mask channels
#define PIX  (Bn*Hn*Wn)    // 131072

// Scratch (static device arrays — no allocation in kernel_launch)
__device__ float g_xt[PIX*Cn];    // x transposed to [b][h][w][c]   (33.5 MB)
__device__ float g_om[PIX*OMC];   // offsets+mask  [b][h][w][27]    (14.2 MB)
__device__ float g_y [PIX*Cn];    // deform conv out [b][h][w][c]   (33.5 MB)
__device__ float g_sum[Cn];
__device__ float g_sq [Cn];

// ---------------------------------------------------------------------------
__global__ void k_zero() {
    int i = threadIdx.x;
    if (i < Cn) { g_sum[i] = 0.f; g_sq[i] = 0.f; }
}

// ---------------------------------------------------------------------------
// x[b][c][h][w] -> xt[((b*H+h)*W+w)*C + c]   (32x32 smem tile transpose)
__global__ __launch_bounds__(1024) void k_transpose_in(const float* __restrict__ x) {
    __shared__ float t[32][33];
    int w0 = blockIdx.x * 32, c0 = blockIdx.y * 32;
    int bh = blockIdx.z;
    int b = bh / Hn, h = bh % Hn;
    int tx = threadIdx.x, ty = threadIdx.y;
    t[ty][tx] = x[(((b*Cn) + (c0+ty))*Hn + h)*Wn + (w0+tx)];
    __syncthreads();
    g_xt[((size_t)bh*Wn + (w0+ty))*Cn + (c0+tx)] = t[tx][ty];
}

// ---------------------------------------------------------------------------
// offset/mask 3x3 conv over 64 input channels -> 27 outputs per pixel.
// One thread per pixel; per-tap weight slice [27][64] staged in smem.
__global__ __launch_bounds__(128) void k_offmask(
    const float* __restrict__ off_w, const float* __restrict__ off_b,
    const float* __restrict__ mod_w, const float* __restrict__ mod_b)
{
    __shared__ float4 wsm[OMC*16];   // [oc][c4] : 27*64 floats = 6.75 KB
    int tid = threadIdx.x;
    int p = blockIdx.x * 128 + tid;
    int b  = p / (Hn*Wn);
    int hw = p % (Hn*Wn);
    int h = hw / Wn, w = hw % Wn;

    float acc[OMC];
    #pragma unroll
    for (int oc = 0; oc < 18; oc++) acc[oc] = off_b[oc];
    #pragma unroll
    for (int j = 0; j < 9; j++)     acc[18+j] = mod_b[j];

    #pragma unroll 1
    for (int tap = 0; tap < 9; tap++) {
        __syncthreads();
        for (int i = tid; i < OMC*Cn; i += 128) {
            int oc = i / Cn, c = i % Cn;
            float v = (oc < 18) ? off_w[(oc*Cn + c)*Kn + tap]
                                : mod_w[((oc-18)*Cn + c)*Kn + tap];
            ((float*)wsm)[i] = v;
        }
        __syncthreads();

        int yy = h + tap/3 - 1;
        int xx = w + tap%3 - 1;
        if (yy < 0 || yy >= Hn || xx < 0 || xx >= Wn) continue;
        const float4* __restrict__ xp =
            (const float4*)&g_xt[(((size_t)b*Hn + yy)*Wn + xx)*Cn];
        #pragma unroll 4
        for (int c4 = 0; c4 < 16; c4++) {
            float4 xv = xp[c4];
            #pragma unroll
            for (int oc = 0; oc < OMC; oc++) {
                float4 wv = wsm[oc*16 + c4];
                acc[oc] += xv.x*wv.x + xv.y*wv.y + xv.z*wv.z + xv.w*wv.w;
            }
        }
    }

    float* op = &g_om[(size_t)p*OMC];
    #pragma unroll
    for (int oc = 0; oc < 18; oc++) op[oc] = acc[oc];
    #pragma unroll
    for (int j = 0; j < 9; j++)
        op[18+j] = 2.0f / (1.0f + expf(-acc[18+j]));   // 2*sigmoid
}

// ---------------------------------------------------------------------------
// Modulated deformable conv: bilinear-gather v[c] per tap (channels-last x),
// multiply by mask, accumulate acc[o] += v[c]*W[o][c][tap].
__global__ __launch_bounds__(128) void k_deform(
    const float* __restrict__ wmat, const float* __restrict__ bias)
{
    __shared__ float4 wsm[Cn*16];   // per-tap weight slice [o][c4] : 16 KB
    int tid = threadIdx.x;
    int p = blockIdx.x * 128 + tid;
    int b  = p / (Hn*Wn);
    int hw = p % (Hn*Wn);
    int h = hw / Wn, w = hw % Wn;

    float acc[Cn];
    #pragma unroll
    for (int o = 0; o < Cn; o++) acc[o] = 0.f;

    const float* __restrict__ omp = &g_om[(size_t)p*OMC];

    #pragma unroll 1
    for (int tap = 0; tap < 9; tap++) {
        __syncthreads();
        for (int i = tid; i < Cn*Cn; i += 128) {
            int o = i / Cn, c = i % Cn;
            ((float*)wsm)[i] = wmat[(o*Cn + c)*Kn + tap];
        }
        __syncthreads();

        float dy = omp[tap*2 + 0];
        float dx = omp[tap*2 + 1];
        float mk = omp[18 + tap];

        float py = (float)(h + tap/3 - 1) + dy;
        float px = (float)(w + tap%3 - 1) + dx;
        float fy = floorf(py), fx = floorf(px);
        float ly = py - fy,    lx = px - fx;
        int y0 = (int)fy, x0 = (int)fx;
        int y1 = y0 + 1,  x1 = x0 + 1;

        float vy0 = (y0 >= 0 && y0 < Hn) ? 1.f : 0.f;
        float vy1 = (y1 >= 0 && y1 < Hn) ? 1.f : 0.f;
        float vx0 = (x0 >= 0 && x0 < Wn) ? 1.f : 0.f;
        float vx1 = (x1 >= 0 && x1 < Wn) ? 1.f : 0.f;

        float w00 = (1.f-ly)*(1.f-lx)*mk * vy0*vx0;
        float w01 = (1.f-ly)*lx       *mk * vy0*vx1;
        float w10 = ly      *(1.f-lx)*mk * vy1*vx0;
        float w11 = ly      *lx       *mk * vy1*vx1;

        int iy0 = min(max(y0,0),Hn-1), iy1 = min(max(y1,0),Hn-1);
        int ix0 = min(max(x0,0),Wn-1), ix1 = min(max(x1,0),Wn-1);

        const float4* __restrict__ p00 = (const float4*)&g_xt[(((size_t)b*Hn+iy0)*Wn+ix0)*Cn];
        const float4* __restrict__ p01 = (const float4*)&g_xt[(((size_t)b*Hn+iy0)*Wn+ix1)*Cn];
        const float4* __restrict__ p10 = (const float4*)&g_xt[(((size_t)b*Hn+iy1)*Wn+ix0)*Cn];
        const float4* __restrict__ p11 = (const float4*)&g_xt[(((size_t)b*Hn+iy1)*Wn+ix1)*Cn];

        #pragma unroll 2
        for (int c4 = 0; c4 < 16; c4++) {
            float4 a = p00[c4], bq = p01[c4], cq = p10[c4], dq = p11[c4];
            float4 v;
            v.x = w00*a.x + w01*bq.x + w10*cq.x + w11*dq.x;
            v.y = w00*a.y + w01*bq.y + w10*cq.y + w11*dq.y;
            v.z = w00*a.z + w01*bq.z + w10*cq.z + w11*dq.z;
            v.w = w00*a.w + w01*bq.w + w10*cq.w + w11*dq.w;
            #pragma unroll
            for (int o = 0; o < Cn; o++) {
                float4 wv = wsm[o*16 + c4];
                acc[o] += v.x*wv.x + v.y*wv.y + v.z*wv.z + v.w*wv.w;
            }
        }
    }

    float4* __restrict__ yp = (float4*)&g_y[(size_t)p*Cn];
    #pragma unroll
    for (int o4 = 0; o4 < 16; o4++) {
        float4 t;
        t.x = acc[o4*4+0] + bias[o4*4+0];
        t.y = acc[o4*4+1] + bias[o4*4+1];
        t.z = acc[o4*4+2] + bias[o4*4+2];
        t.w = acc[o4*4+3] + bias[o4*4+3];
        yp[o4] = t;
    }
}

// ---------------------------------------------------------------------------
// Per-channel sum / sumsq over all B*H*W pixels (channels-last reads).
__global__ __launch_bounds__(256) void k_stats() {
    __shared__ float s_sum[Cn], s_sq[Cn];
    int tid = threadIdx.x;
    if (tid < Cn) { s_sum[tid] = 0.f; s_sq[tid] = 0.f; }
    __syncthreads();

    int lane = tid & 31, warp = tid >> 5;
    int gw = blockIdx.x * 8 + warp;                  // 256 blocks * 8 warps = 2048
    const int per = PIX / 2048;                      // 64 pixels per warp
    float s0 = 0.f, s1 = 0.f, q0 = 0.f, q1 = 0.f;
    for (int i = 0; i < per; i++) {
        size_t p = (size_t)gw*per + i;
        float a = g_y[p*Cn + lane];
        float c = g_y[p*Cn + 32 + lane];
        s0 += a; q0 += a*a;
        s1 += c; q1 += c*c;
    }
    atomicAdd(&s_sum[lane],      s0);
    atomicAdd(&s_sum[32 + lane], s1);
    atomicAdd(&s_sq [lane],      q0);
    atomicAdd(&s_sq [32 + lane], q1);
    __syncthreads();
    if (tid < Cn) {
        atomicAdd(&g_sum[tid], s_sum[tid]);
        atomicAdd(&g_sq [tid], s_sq [tid]);
    }
}

// ---------------------------------------------------------------------------
// Normalize + affine + ReLU, and transpose NHWC -> NCHW into d_out.
__global__ __launch_bounds__(1024) void k_norm_out(
    const float* __restrict__ gamma, const float* __restrict__ beta,
    float* __restrict__ out)
{
    __shared__ float t[32][33];
    int w0 = blockIdx.x * 32, c0 = blockIdx.y * 32;
    int bh = blockIdx.z;
    int b = bh / Hn, h = bh % Hn;
    int tx = threadIdx.x, ty = threadIdx.y;

    int c = c0 + tx;
    const float inv = 1.0f / (float)PIX;
    float mean = g_sum[c] * inv;
    float var  = g_sq[c] * inv - mean*mean;
    float rstd = rsqrtf(var + 1e-5f);
    float sc = gamma[c] * rstd;
    float sh = beta[c] - mean * sc;

    float v = g_y[((size_t)bh*Wn + (w0+ty))*Cn + c];
    t[ty][tx] = fmaxf(v*sc + sh, 0.f);
    __syncthreads();
    out[(((size_t)b*Cn + (c0+ty))*Hn + h)*Wn + (w0+tx)] = t[tx][ty];
}

// ---------------------------------------------------------------------------
extern "C" void kernel_launch(void* const* d_in, const int* in_sizes, int n_in,
                              void* d_out, int out_size)
{
    const float* x     = (const float*)d_in[0];
    const float* off_w = (const float*)d_in[1];
    const float* off_b = (const float*)d_in[2];
    const float* mod_w = (const float*)d_in[3];
    const float* mod_b = (const float*)d_in[4];
    const float* wmat  = (const float*)d_in[5];
    const float* bias  = (const float*)d_in[6];
    const float* gamma = (const float*)d_in[7];
    const float* beta  = (const float*)d_in[8];
    float* out = (float*)d_out;

    dim3 tgrid(Wn/32, Cn/32, Bn*Hn);
    dim3 tblk(32, 32);

    k_zero<<<1, 64>>>();
    k_transpose_in<<<tgrid, tblk>>>(x);
    k_offmask<<<PIX/128, 128>>>(off_w, off_b, mod_w, mod_b);
    k_deform <<<PIX/128, 128>>>(wmat, bias);
    k_stats  <<<256, 256>>>();
    k_norm_out<<<tgrid, tblk>>>(gamma, beta, out);
}

// round 2
// speedup vs baseline: 1.2098x; 1.2098x over previous
#include <cuda_runtime.h>
#include <math.h>

#define Bn   8
#define Cn   64
#define Hn   128
#define Wn   128
#define PIX  (Bn*Hn*Wn)    // 131072

// Scratch (static device arrays — no allocation anywhere)
__device__ float g_xt[PIX*Cn];        // x channels-last [b][h][w][c]
__device__ float g_om[PIX*27];        // offsets+mask   [pix][27]
__device__ float g_y [PIX*Cn];        // deform out     [pix][c]
__device__ float g_wt  [9*64*64];     // deform weights [tap][c][o]
__device__ float g_wtom[9*64*32];     // off/mask wts   [tap][c][o(pad32)]
__device__ float g_sum[Cn];
__device__ float g_sq [Cn];

// Packed fp32x2 FMA (sm_103a): d = a*b + d on two lanes
#define FFMA2(d,a,b) asm("fma.rn.f32x2 %0, %1, %2, %0;" : "+l"(d) : "l"(a), "l"(b))
#define DUP2(d,s)    asm("mov.b64 %0, {%1, %1};"        : "=l"(d) : "f"(s))
#define UNPK2(lo,hi,s) asm("mov.b64 {%0, %1}, %2;" : "=f"(lo), "=f"(hi) : "l"(s))

// ---------------------------------------------------------------------------
__global__ void k_zero() {
    int i = threadIdx.x;
    if (i < Cn) { g_sum[i] = 0.f; g_sq[i] = 0.f; }
}

// ---------------------------------------------------------------------------
// Pre-transpose weights: wmat[o][c][tap] -> g_wt[tap][c][o]; off/mod -> g_wtom
__global__ __launch_bounds__(256) void k_wprep(
    const float* __restrict__ wmat,
    const float* __restrict__ off_w, const float* __restrict__ mod_w)
{
    for (int i = blockIdx.x*256 + threadIdx.x; i < 9*64*64; i += gridDim.x*256) {
        int tap = i / 4096, r = i % 4096;
        int c = r >> 6, o = r & 63;
        g_wt[i] = wmat[(o*64 + c)*9 + tap];
        if (o < 32) {
            float v = 0.f;
            if (o < 18)      v = off_w[(o*64 + c)*9 + tap];
            else if (o < 27) v = mod_w[((o-18)*64 + c)*9 + tap];
            g_wtom[(tap*64 + c)*32 + o] = v;
        }
    }
}

// ---------------------------------------------------------------------------
// x[b][c][h][w] -> g_xt[((b*H+h)*W+w)*C + c]
__global__ __launch_bounds__(1024) void k_transpose_in(const float* __restrict__ x) {
    __shared__ float t[32][33];
    int w0 = blockIdx.x * 32, c0 = blockIdx.y * 32;
    int bh = blockIdx.z;
    int b = bh / Hn, h = bh % Hn;
    int tx = threadIdx.x, ty = threadIdx.y;
    t[ty][tx] = x[(((b*Cn) + (c0+ty))*Hn + h)*Wn + (w0+tx)];
    __syncthreads();
    g_xt[((size_t)bh*Wn + (w0+ty))*Cn + (c0+tx)] = t[tx][ty];
}

// ---------------------------------------------------------------------------
// offset/mask conv as per-tap GEMM: 128 pixels x 32 outs (27 used), FFMA2.
// 64 threads: tile = 8 pixels x 8 outs.
__global__ __launch_bounds__(64) void k_offmask(
    const float* __restrict__ off_b, const float* __restrict__ mod_b)
{
    __shared__ __align__(16) float vsm[64*128];   // [k][pix]
    __shared__ __align__(16) float wsm[64*32];    // [k][o]
    int tid = threadIdx.x;
    int blk = blockIdx.x;
    int b = blk >> 7, h = blk & 127;
    int p0 = blk * 128;
    int pm = tid & 15, og = tid >> 4;             // pm:pixel group, og:out group 0..3

    unsigned long long acc[32];
    #pragma unroll
    for (int i = 0; i < 32; i++) acc[i] = 0ULL;

    for (int tap = 0; tap < 9; tap++) {
        __syncthreads();
        // stage weights (coalesced from pre-transposed g_wtom)
        {
            const float4* src = (const float4*)&g_wtom[tap*64*32];
            float4* dst = (float4*)wsm;
            for (int i = tid; i < 64*32/4; i += 64) dst[i] = src[i];
        }
        // stage shifted x rows into vsm[k][pix] (2 pixels per thread)
        int yy = h + tap/3 - 1;
        int dxs = tap%3 - 1;
        #pragma unroll
        for (int s = 0; s < 2; s++) {
            int wcol = tid + s*64;
            int xx = wcol + dxs;
            bool ok = (yy >= 0) && (yy < Hn) && (xx >= 0) && (xx < Wn);
            const float4* xp = ok ? (const float4*)&g_xt[(((size_t)b*Hn + yy)*Wn + xx)*Cn]
                                  : (const float4*)0;
            #pragma unroll 4
            for (int c4 = 0; c4 < 16; c4++) {
                float4 v = ok ? xp[c4] : make_float4(0.f,0.f,0.f,0.f);
                vsm[(c4*4+0)*128 + wcol] = v.x;
                vsm[(c4*4+1)*128 + wcol] = v.y;
                vsm[(c4*4+2)*128 + wcol] = v.z;
                vsm[(c4*4+3)*128 + wcol] = v.w;
            }
        }
        __syncthreads();
        // GEMM: 64 k-steps
        #pragma unroll 2
        for (int k = 0; k < 64; k++) {
            ulonglong2 va = *(const ulonglong2*)&vsm[k*128 + pm*8];
            ulonglong2 vb = *(const ulonglong2*)&vsm[k*128 + pm*8 + 4];
            float4 w0 = *(const float4*)&wsm[k*32 + og*8];
            float4 w1 = *(const float4*)&wsm[k*32 + og*8 + 4];
            unsigned long long wd[8];
            DUP2(wd[0], w0.x); DUP2(wd[1], w0.y); DUP2(wd[2], w0.z); DUP2(wd[3], w0.w);
            DUP2(wd[4], w1.x); DUP2(wd[5], w1.y); DUP2(wd[6], w1.z); DUP2(wd[7], w1.w);
            #pragma unroll
            for (int o = 0; o < 8; o++) {
                FFMA2(acc[0*8+o], va.x, wd[o]);
                FFMA2(acc[1*8+o], va.y, wd[o]);
                FFMA2(acc[2*8+o], vb.x, wd[o]);
                FFMA2(acc[3*8+o], vb.y, wd[o]);
            }
        }
    }
    // epilogue: bias + sigmoid for mask channels, store to g_om[pix][27]
    float bo[8];
    #pragma unroll
    for (int j = 0; j < 8; j++) {
        int o = og*8 + j;
        bo[j] = (o < 18) ? off_b[o] : (o < 27 ? mod_b[o-18] : 0.f);
    }
    #pragma unroll
    for (int pp2 = 0; pp2 < 4; pp2++) {
        int pa = p0 + pm*8 + pp2*2;
        #pragma unroll
        for (int j = 0; j < 8; j++) {
            int o = og*8 + j;
            if (o >= 27) continue;
            float lo, hi; UNPK2(lo, hi, acc[pp2*8+j]);
            lo += bo[j]; hi += bo[j];
            if (o >= 18) {
                lo = 2.0f / (1.0f + expf(-lo));
                hi = 2.0f / (1.0f + expf(-hi));
            }
            g_om[(size_t)pa*27 + o]     = lo;
            g_om[(size_t)(pa+1)*27 + o] = hi;
        }
    }
}

// ---------------------------------------------------------------------------
// Deformable conv as per-tap GEMM: 128 pixels x 64 outs, FFMA2.
// 128 threads: gather phase = 1 pixel/thread; GEMM tile = 8 pixels x 8 outs.
// Fused BN partial stats.
__global__ __launch_bounds__(128, 3) void k_deform(const float* __restrict__ bias)
{
    __shared__ __align__(16) float vsm[64*128];   // [k][pix]  32 KB
    __shared__ __align__(16) float wsm[64*64];    // [k][o]    16 KB
    int tid = threadIdx.x;
    int blk = blockIdx.x;
    int b = blk >> 7, h = blk & 127;
    int p0 = blk * 128;
    int pm = tid & 15, og = tid >> 4;             // og 0..7

    unsigned long long acc[32];
    #pragma unroll
    for (int i = 0; i < 32; i++) acc[i] = 0ULL;

    for (int tap = 0; tap < 9; tap++) {
        __syncthreads();
        // stage weights (coalesced)
        {
            const float4* src = (const float4*)&g_wt[tap*64*64];
            float4* dst = (float4*)wsm;
            for (int i = tid; i < 64*64/4; i += 128) dst[i] = src[i];
        }
        // gather + bilinear blend: thread = pixel tid
        {
            int wcol = tid;
            const float* omp = &g_om[(size_t)(p0+tid)*27];
            float dy = omp[tap*2], dx = omp[tap*2+1], mk = omp[18+tap];
            float py = (float)(h + tap/3 - 1) + dy;
            float px = (float)(wcol + tap%3 - 1) + dx;
            float fy = floorf(py), fx = floorf(px);
            float ly = py - fy,    lx = px - fx;
            int y0 = (int)fy, x0 = (int)fx;
            int y1 = y0 + 1,  x1 = x0 + 1;
            float vy0 = (y0 >= 0 && y0 < Hn) ? 1.f : 0.f;
            float vy1 = (y1 >= 0 && y1 < Hn) ? 1.f : 0.f;
            float vx0 = (x0 >= 0 && x0 < Wn) ? 1.f : 0.f;
            float vx1 = (x1 >= 0 && x1 < Wn) ? 1.f : 0.f;
            float w00 = (1.f-ly)*(1.f-lx)*mk * vy0*vx0;
            float w01 = (1.f-ly)*lx      *mk * vy0*vx1;
            float w10 = ly      *(1.f-lx)*mk * vy1*vx0;
            float w11 = ly      *lx      *mk * vy1*vx1;
            int iy0 = min(max(y0,0),Hn-1), iy1 = min(max(y1,0),Hn-1);
            int ix0 = min(max(x0,0),Wn-1), ix1 = min(max(x1,0),Wn-1);
            const float4* pA = (const float4*)&g_xt[(((size_t)b*Hn+iy0)*Wn+ix0)*Cn];
            const float4* pB = (const float4*)&g_xt[(((size_t)b*Hn+iy0)*Wn+ix1)*Cn];
            const float4* pC = (const float4*)&g_xt[(((size_t)b*Hn+iy1)*Wn+ix0)*Cn];
            const float4* pD = (const float4*)&g_xt[(((size_t)b*Hn+iy1)*Wn+ix1)*Cn];
            #pragma unroll 4
            for (int c4 = 0; c4 < 16; c4++) {
                float4 a = pA[c4], e = pB[c4], c = pC[c4], d = pD[c4];
                float4 v;
                v.x = w00*a.x + w01*e.x + w10*c.x + w11*d.x;
                v.y = w00*a.y + w01*e.y + w10*c.y + w11*d.y;
                v.z = w00*a.z + w01*e.z + w10*c.z + w11*d.z;
                v.w = w00*a.w + w01*e.w + w10*c.w + w11*d.w;
                vsm[(c4*4+0)*128 + wcol] = v.x;
                vsm[(c4*4+1)*128 + wcol] = v.y;
                vsm[(c4*4+2)*128 + wcol] = v.z;
                vsm[(c4*4+3)*128 + wcol] = v.w;
            }
        }
        __syncthreads();
        // GEMM: 64 k-steps
        #pragma unroll 2
        for (int k = 0; k < 64; k++) {
            ulonglong2 va = *(const ulonglong2*)&vsm[k*128 + pm*8];
            ulonglong2 vb = *(const ulonglong2*)&vsm[k*128 + pm*8 + 4];
            float4 w0 = *(const float4*)&wsm[k*64 + og*8];
            float4 w1 = *(const float4*)&wsm[k*64 + og*8 + 4];
            unsigned long long wd[8];
            DUP2(wd[0], w0.x); DUP2(wd[1], w0.y); DUP2(wd[2], w0.z); DUP2(wd[3], w0.w);
            DUP2(wd[4], w1.x); DUP2(wd[5], w1.y); DUP2(wd[6], w1.z); DUP2(wd[7], w1.w);
            #pragma unroll
            for (int o = 0; o < 8; o++) {
                FFMA2(acc[0*8+o], va.x, wd[o]);
                FFMA2(acc[1*8+o], va.y, wd[o]);
                FFMA2(acc[2*8+o], vb.x, wd[o]);
                FFMA2(acc[3*8+o], vb.y, wd[o]);
            }
        }
    }
    // epilogue: + bias, store y, fused BN partial sums
    float bo[8], ysum[8], ysq[8];
    #pragma unroll
    for (int j = 0; j < 8; j++) { bo[j] = bias[og*8+j]; ysum[j] = 0.f; ysq[j] = 0.f; }
    #pragma unroll
    for (int pp2 = 0; pp2 < 4; pp2++) {
        int pa = p0 + pm*8 + pp2*2;
        float4 lo0, lo1, hi0, hi1;
        float l, hgh;
        UNPK2(l, hgh, acc[pp2*8+0]); lo0.x = l+bo[0]; hi0.x = hgh+bo[0];
        UNPK2(l, hgh, acc[pp2*8+1]); lo0.y = l+bo[1]; hi0.y = hgh+bo[1];
        UNPK2(l, hgh, acc[pp2*8+2]); lo0.z = l+bo[2]; hi0.z = hgh+bo[2];
        UNPK2(l, hgh, acc[pp2*8+3]); lo0.w = l+bo[3]; hi0.w = hgh+bo[3];
        UNPK2(l, hgh, acc[pp2*8+4]); lo1.x = l+bo[4]; hi1.x = hgh+bo[4];
        UNPK2(l, hgh, acc[pp2*8+5]); lo1.y = l+bo[5]; hi1.y = hgh+bo[5];
        UNPK2(l, hgh, acc[pp2*8+6]); lo1.z = l+bo[6]; hi1.z = hgh+bo[6];
        UNPK2(l, hgh, acc[pp2*8+7]); lo1.w = l+bo[7]; hi1.w = hgh+bo[7];
        *(float4*)&g_y[(size_t)pa*64     + og*8]     = lo0;
        *(float4*)&g_y[(size_t)pa*64     + og*8 + 4] = lo1;
        *(float4*)&g_y[(size_t)(pa+1)*64 + og*8]     = hi0;
        *(float4*)&g_y[(size_t)(pa+1)*64 + og*8 + 4] = hi1;
        ysum[0] += lo0.x + hi0.x; ysq[0] += lo0.x*lo0.x + hi0.x*hi0.x;
        ysum[1] += lo0.y + hi0.y; ysq[1] += lo0.y*lo0.y + hi0.y*hi0.y;
        ysum[2] += lo0.z + hi0.z; ysq[2] += lo0.z*lo0.z + hi0.z*hi0.z;
        ysum[3] += lo0.w + hi0.w; ysq[3] += lo0.w*lo0.w + hi0.w*hi0.w;
        ysum[4] += lo1.x + hi1.x; ysq[4] += lo1.x*lo1.x + hi1.x*hi1.x;
        ysum[5] += lo1.y + hi1.y; ysq[5] += lo1.y*lo1.y + hi1.y*hi1.y;
        ysum[6] += lo1.z + hi1.z; ysq[6] += lo1.z*lo1.z + hi1.z*hi1.z;
        ysum[7] += lo1.w + hi1.w; ysq[7] += lo1.w*lo1.w + hi1.w*hi1.w;
    }
    // reduce over pm within each 16-lane group (og constant per group)
    #pragma unroll
    for (int d = 1; d < 16; d <<= 1) {
        #pragma unroll
        for (int j = 0; j < 8; j++) {
            ysum[j] += __shfl_xor_sync(0xffffffffu, ysum[j], d);
            ysq [j] += __shfl_xor_sync(0xffffffffu, ysq [j], d);
        }
    }
    if (pm == 0) {
        #pragma unroll
        for (int j = 0; j < 8; j++) {
            atomicAdd(&g_sum[og*8+j], ysum[j]);
            atomicAdd(&g_sq [og*8+j], ysq [j]);
        }
    }
}

// ---------------------------------------------------------------------------
// Normalize + affine + ReLU, NHWC -> NCHW into d_out.
__global__ __launch_bounds__(1024) void k_norm_out(
    const float* __restrict__ gamma, const float* __restrict__ beta,
    float* __restrict__ out)
{
    __shared__ float t[32][33];
    int w0 = blockIdx.x * 32, c0 = blockIdx.y * 32;
    int bh = blockIdx.z;
    int b = bh / Hn, h = bh % Hn;
    int tx = threadIdx.x, ty = threadIdx.y;

    int c = c0 + tx;
    const float inv = 1.0f / (float)PIX;
    float mean = g_sum[c] * inv;
    float var  = g_sq[c] * inv - mean*mean;
    float rstd = rsqrtf(var + 1e-5f);
    float sc = gamma[c] * rstd;
    float sh = beta[c] - mean * sc;

    float v = g_y[((size_t)bh*Wn + (w0+ty))*Cn + c];
    t[ty][tx] = fmaxf(v*sc + sh, 0.f);
    __syncthreads();
    out[(((size_t)b*Cn + (c0+ty))*Hn + h)*Wn + (w0+tx)] = t[tx][ty];
}

// ---------------------------------------------------------------------------
extern "C" void kernel_launch(void* const* d_in, const int* in_sizes, int n_in,
                              void* d_out, int out_size)
{
    const float* x     = (const float*)d_in[0];
    const float* off_w = (const float*)d_in[1];
    const float* off_b = (const float*)d_in[2];
    const float* mod_w = (const float*)d_in[3];
    const float* mod_b = (const float*)d_in[4];
    const float* wmat  = (const float*)d_in[5];
    const float* bias  = (const float*)d_in[6];
    const float* gamma = (const float*)d_in[7];
    const float* beta  = (const float*)d_in[8];
    float* out = (float*)d_out;

    dim3 tgrid(Wn/32, Cn/32, Bn*Hn);
    dim3 tblk(32, 32);

    k_zero<<<1, 64>>>();
    k_wprep<<<64, 256>>>(wmat, off_w, mod_w);
    k_transpose_in<<<tgrid, tblk>>>(x);
    k_offmask<<<PIX/128, 64>>>(off_b, mod_b);
    k_deform <<<PIX/128, 128>>>(bias);
    k_norm_out<<<tgrid, tblk>>>(gamma, beta, out);
}

// round 3
// speedup vs baseline: 1.5334x; 1.2674x over previous
#include <cuda_runtime.h>
#include <math.h>

#define Bn   8
#define Cn   64
#define Hn   128
#define Wn   128
#define PIX  (Bn*Hn*Wn)    // 131072

// Scratch (static device arrays — no allocation anywhere)
__device__ float g_xt[PIX*Cn];        // x channels-last [b][h][w][c]
__device__ float g_om[PIX*27];        // offsets+mask   [pix][27]
__device__ float g_y [PIX*Cn];        // deform out     [pix][c]
__device__ float g_wt  [9*64*64];     // deform weights [tap][c][o]
__device__ float g_wtom[9*64*32];     // off/mask wts   [tap][c][o(pad32)]
__device__ float g_sum[Cn];
__device__ float g_sq [Cn];

// Packed fp32x2 FMA (sm_103a)
#define FFMA2(d,a,b) asm("fma.rn.f32x2 %0, %1, %2, %0;" : "+l"(d) : "l"(a), "l"(b))
#define DUP2(d,s)    asm("mov.b64 %0, {%1, %1};"        : "=l"(d) : "f"(s))
#define UNPK2(lo,hi,s) asm("mov.b64 {%0, %1}, %2;" : "=f"(lo), "=f"(hi) : "l"(s))

#define OSTR 66               // offmask vsm pixel stride (conflict-free: pg*66%32 = 2*pg)
#define DSTR 68               // deform  vsm pixel stride (conflict-free: pg*68%32 = 4*pg, 8 pg/warp)
#define OFF_SMEM ((3*130*OSTR + 64*32)*4)
#define DEF_SMEM ((128*DSTR + 64*64 + 128*8)*4)

// ---------------------------------------------------------------------------
__global__ void k_zero() {
    int i = threadIdx.x;
    if (i < Cn) { g_sum[i] = 0.f; g_sq[i] = 0.f; }
}

// ---------------------------------------------------------------------------
// wmat[o][c][tap] -> g_wt[tap][c][o]; off/mod -> g_wtom[tap][c][o(pad32)]
__global__ __launch_bounds__(256) void k_wprep(
    const float* __restrict__ wmat,
    const float* __restrict__ off_w, const float* __restrict__ mod_w)
{
    for (int i = blockIdx.x*256 + threadIdx.x; i < 9*64*64; i += gridDim.x*256) {
        int tap = i / 4096, r = i % 4096;
        int c = r >> 6, o = r & 63;
        g_wt[i] = wmat[(o*64 + c)*9 + tap];
        if (o < 32) {
            float v = 0.f;
            if (o < 18)      v = off_w[(o*64 + c)*9 + tap];
            else if (o < 27) v = mod_w[((o-18)*64 + c)*9 + tap];
            g_wtom[(tap*64 + c)*32 + o] = v;
        }
    }
}

// ---------------------------------------------------------------------------
// x[b][c][h][w] -> g_xt[((b*H+h)*W+w)*C + c]
__global__ __launch_bounds__(1024) void k_transpose_in(const float* __restrict__ x) {
    __shared__ float t[32][33];
    int w0 = blockIdx.x * 32, c0 = blockIdx.y * 32;
    int bh = blockIdx.z;
    int b = bh / Hn, h = bh % Hn;
    int tx = threadIdx.x, ty = threadIdx.y;
    t[ty][tx] = x[(((b*Cn) + (c0+ty))*Hn + h)*Wn + (w0+tx)];
    __syncthreads();
    g_xt[((size_t)bh*Wn + (w0+ty))*Cn + (c0+tx)] = t[tx][ty];
}

// ---------------------------------------------------------------------------
// offset/mask conv: block = 1 row (128 px). x-tile (3 rows + halo) staged ONCE.
// 128 threads: og=tid&1 (16 outs), pg=tid>>1 (px {pg, pg+64}).
__global__ __launch_bounds__(128, 2) void k_offmask(
    const float* __restrict__ off_b, const float* __restrict__ mod_b)
{
    extern __shared__ float sm[];
    float* vsm = sm;                    // [3*130][OSTR] channels at stride 1
    float* wsm = sm + 3*130*OSTR;       // [64][32]
    int tid = threadIdx.x;
    int blk = blockIdx.x;
    int b = blk >> 7, h = blk & 127;
    int p0 = blk * 128;
    int og = tid & 1, pg = tid >> 1;

    // stage x tile: rows h-1..h+1, halo cols -1..128 (130 wide)
    for (int t = tid; t < 3*130*32; t += 128) {
        int c2 = t & 31;
        int rc = t >> 5;                  // r*130 + hx
        int r = rc / 130, hx = rc - r*130;
        int y = h + r - 1, xx = hx - 1;
        float2 v = make_float2(0.f, 0.f);
        if (y >= 0 && y < Hn && xx >= 0 && xx < Wn)
            v = *(const float2*)&g_xt[(((size_t)b*Hn + y)*Wn + xx)*Cn + c2*2];
        *(float2*)&vsm[(size_t)rc*OSTR + c2*2] = v;
    }

    unsigned long long acc[16];           // [i(2 px)][8 out-pairs]
    #pragma unroll
    for (int i = 0; i < 16; i++) acc[i] = 0ULL;

    for (int tap = 0; tap < 9; tap++) {
        __syncthreads();
        {   // stage weights for this tap: [64 c][32 o]
            const float4* src = (const float4*)&g_wtom[tap*2048];
            float4* dst = (float4*)wsm;
            for (int i = tid; i < 512; i += 128) dst[i] = src[i];
        }
        __syncthreads();
        int r = tap/3, tx = tap - r*3;
        const float* v0p = &vsm[(r*130 + tx + pg     )*OSTR];
        const float* v1p = &vsm[(r*130 + tx + pg + 64)*OSTR];
        #pragma unroll 2
        for (int c = 0; c < 64; c++) {
            float va = v0p[c], vb = v1p[c];
            unsigned long long da, db;
            DUP2(da, va); DUP2(db, vb);
            const ulonglong2* wp = (const ulonglong2*)&wsm[c*32 + og*16];
            ulonglong2 q0 = wp[0], q1 = wp[1], q2 = wp[2], q3 = wp[3];
            FFMA2(acc[0], da, q0.x); FFMA2(acc[1], da, q0.y);
            FFMA2(acc[2], da, q1.x); FFMA2(acc[3], da, q1.y);
            FFMA2(acc[4], da, q2.x); FFMA2(acc[5], da, q2.y);
            FFMA2(acc[6], da, q3.x); FFMA2(acc[7], da, q3.y);
            FFMA2(acc[8],  db, q0.x); FFMA2(acc[9],  db, q0.y);
            FFMA2(acc[10], db, q1.x); FFMA2(acc[11], db, q1.y);
            FFMA2(acc[12], db, q2.x); FFMA2(acc[13], db, q2.y);
            FFMA2(acc[14], db, q3.x); FFMA2(acc[15], db, q3.y);
        }
    }

    // epilogue: bias + sigmoid for mask channels
    #pragma unroll
    for (int i = 0; i < 2; i++) {
        int px = p0 + pg + i*64;
        #pragma unroll
        for (int j = 0; j < 8; j++) {
            int o = og*16 + 2*j;
            float lo, hi; UNPK2(lo, hi, acc[i*8 + j]);
            if (o < 27) {
                float bv = (o < 18) ? off_b[o] : mod_b[o-18];
                lo += bv;
                if (o >= 18) lo = 2.0f / (1.0f + expf(-lo));
                g_om[(size_t)px*27 + o] = lo;
            }
            if (o+1 < 27) {
                float bv = (o+1 < 18) ? off_b[o+1] : mod_b[o+1-18];
                hi += bv;
                if (o+1 >= 18) hi = 2.0f / (1.0f + expf(-hi));
                g_om[(size_t)px*27 + o+1] = hi;
            }
        }
    }
}

// ---------------------------------------------------------------------------
// Deformable conv: block = 1 row (128 px), 128 threads.
// Per tap: params (1 thr/px) -> cooperative gather (16 lanes/px) -> GEMM.
// GEMM tile: og=tid&3 (16 outs), pg=tid>>2, px = pg + i*32 (i 0..3).
__global__ __launch_bounds__(128, 4) void k_deform(const float* __restrict__ bias)
{
    extern __shared__ float sm[];
    float* vsm = sm;                     // [128 px][DSTR]
    float* wsm = sm + 128*DSTR;          // [64 c][64 o]
    float* psm = wsm + 64*64;            // [128 px][8] params (also stats scratch)
    int tid = threadIdx.x;
    int blk = blockIdx.x;
    int b = blk >> 7, h = blk & 127;
    int p0 = blk * 128;
    int og = tid & 3, pg = tid >> 2;

    unsigned long long acc[32];          // [i(4 px)][8 out-pairs]
    #pragma unroll
    for (int i = 0; i < 32; i++) acc[i] = 0ULL;

    for (int tap = 0; tap < 9; tap++) {
        __syncthreads();
        {   // stage weights [64 c][64 o]
            const float4* src = (const float4*)&g_wt[tap*4096];
            float4* dst = (float4*)wsm;
            for (int i = tid; i < 1024; i += 128) dst[i] = src[i];
        }
        {   // params: thread = pixel
            const float* omp = &g_om[(size_t)(p0 + tid)*27];
            float dy = omp[tap*2], dx = omp[tap*2+1], mk = omp[18+tap];
            float py = (float)(h + tap/3 - 1) + dy;
            float px_ = (float)(tid + tap%3 - 1) + dx;
            float fy = floorf(py), fx = floorf(px_);
            float ly = py - fy,    lx = px_ - fx;
            int y0 = (int)fy, x0 = (int)fx;
            int y1 = y0 + 1,  x1 = x0 + 1;
            float vy0 = (y0 >= 0 && y0 < Hn) ? 1.f : 0.f;
            float vy1 = (y1 >= 0 && y1 < Hn) ? 1.f : 0.f;
            float vx0 = (x0 >= 0 && x0 < Wn) ? 1.f : 0.f;
            float vx1 = (x1 >= 0 && x1 < Wn) ? 1.f : 0.f;
            int iy0 = min(max(y0,0),Hn-1), iy1 = min(max(y1,0),Hn-1);
            int ix0 = min(max(x0,0),Wn-1), ix1 = min(max(x1,0),Wn-1);
            int base = (b*Hn)*Wn;
            psm[tid*8+0] = (1.f-ly)*(1.f-lx)*mk * vy0*vx0;
            psm[tid*8+1] = (1.f-ly)*lx      *mk * vy0*vx1;
            psm[tid*8+2] = ly      *(1.f-lx)*mk * vy1*vx0;
            psm[tid*8+3] = ly      *lx      *mk * vy1*vx1;
            psm[tid*8+4] = __int_as_float(((base + iy0*Wn + ix0)*Cn) >> 2);
            psm[tid*8+5] = __int_as_float(((base + iy0*Wn + ix1)*Cn) >> 2);
            psm[tid*8+6] = __int_as_float(((base + iy1*Wn + ix0)*Cn) >> 2);
            psm[tid*8+7] = __int_as_float(((base + iy1*Wn + ix1)*Cn) >> 2);
        }
        __syncthreads();
        {   // cooperative gather: 8 groups of 16 lanes; lane = c4
            int grp = tid >> 4, c4 = tid & 15;
            const float4* P = (const float4*)g_xt;
            #pragma unroll 2
            for (int it = 0; it < 16; it++) {
                int px = it*8 + grp;
                float w00 = psm[px*8+0], w01 = psm[px*8+1];
                float w10 = psm[px*8+2], w11 = psm[px*8+3];
                int i00 = __float_as_int(psm[px*8+4]);
                int i01 = __float_as_int(psm[px*8+5]);
                int i10 = __float_as_int(psm[px*8+6]);
                int i11 = __float_as_int(psm[px*8+7]);
                float4 a = P[i00 + c4], e = P[i01 + c4];
                float4 c = P[i10 + c4], d = P[i11 + c4];
                float4 v;
                v.x = w00*a.x + w01*e.x + w10*c.x + w11*d.x;
                v.y = w00*a.y + w01*e.y + w10*c.y + w11*d.y;
                v.z = w00*a.z + w01*e.z + w10*c.z + w11*d.z;
                v.w = w00*a.w + w01*e.w + w10*c.w + w11*d.w;
                *(float4*)&vsm[px*DSTR + c4*4] = v;
            }
        }
        __syncthreads();
        // GEMM: 64 k-steps over channels
        #pragma unroll 2
        for (int c = 0; c < 64; c++) {
            float f0 = vsm[(pg     )*DSTR + c];
            float f1 = vsm[(pg + 32)*DSTR + c];
            float f2 = vsm[(pg + 64)*DSTR + c];
            float f3 = vsm[(pg + 96)*DSTR + c];
            unsigned long long d0, d1, d2, d3;
            DUP2(d0, f0); DUP2(d1, f1); DUP2(d2, f2); DUP2(d3, f3);
            const ulonglong2* wp = (const ulonglong2*)&wsm[c*64 + og*16];
            ulonglong2 q0 = wp[0], q1 = wp[1], q2 = wp[2], q3 = wp[3];
            FFMA2(acc[0], d0, q0.x); FFMA2(acc[1], d0, q0.y);
            FFMA2(acc[2], d0, q1.x); FFMA2(acc[3], d0, q1.y);
            FFMA2(acc[4], d0, q2.x); FFMA2(acc[5], d0, q2.y);
            FFMA2(acc[6], d0, q3.x); FFMA2(acc[7], d0, q3.y);
            FFMA2(acc[8],  d1, q0.x); FFMA2(acc[9],  d1, q0.y);
            FFMA2(acc[10], d1, q1.x); FFMA2(acc[11], d1, q1.y);
            FFMA2(acc[12], d1, q2.x); FFMA2(acc[13], d1, q2.y);
            FFMA2(acc[14], d1, q3.x); FFMA2(acc[15], d1, q3.y);
            FFMA2(acc[16], d2, q0.x); FFMA2(acc[17], d2, q0.y);
            FFMA2(acc[18], d2, q1.x); FFMA2(acc[19], d2, q1.y);
            FFMA2(acc[20], d2, q2.x); FFMA2(acc[21], d2, q2.y);
            FFMA2(acc[22], d2, q3.x); FFMA2(acc[23], d2, q3.y);
            FFMA2(acc[24], d3, q0.x); FFMA2(acc[25], d3, q0.y);
            FFMA2(acc[26], d3, q1.x); FFMA2(acc[27], d3, q1.y);
            FFMA2(acc[28], d3, q2.x); FFMA2(acc[29], d3, q2.y);
            FFMA2(acc[30], d3, q3.x); FFMA2(acc[31], d3, q3.y);
        }
    }

    // epilogue: +bias, store y, BN partial stats
    float bo[16], ysum[16], ysq[16];
    #pragma unroll
    for (int j = 0; j < 16; j++) { bo[j] = bias[og*16+j]; ysum[j] = 0.f; ysq[j] = 0.f; }
    #pragma unroll
    for (int i = 0; i < 4; i++) {
        int px = p0 + pg + i*32;
        float vals[16];
        #pragma unroll
        for (int j = 0; j < 8; j++) {
            float lo, hi; UNPK2(lo, hi, acc[i*8 + j]);
            vals[2*j]   = lo + bo[2*j];
            vals[2*j+1] = hi + bo[2*j+1];
        }
        #pragma unroll
        for (int k = 0; k < 4; k++)
            *(float4*)&g_y[(size_t)px*64 + og*16 + k*4] = *(float4*)&vals[k*4];
        #pragma unroll
        for (int j = 0; j < 16; j++) { ysum[j] += vals[j]; ysq[j] += vals[j]*vals[j]; }
    }
    // reduce across lanes sharing og (lanes differ in bits 2..4)
    #pragma unroll
    for (int d = 4; d < 32; d <<= 1) {
        #pragma unroll
        for (int j = 0; j < 16; j++) {
            ysum[j] += __shfl_xor_sync(0xffffffffu, ysum[j], d);
            ysq [j] += __shfl_xor_sync(0xffffffffu, ysq [j], d);
        }
    }
    __syncthreads();
    if (tid < 128) psm[tid] = 0.f;
    __syncthreads();
    if ((tid & 31) < 4) {
        #pragma unroll
        for (int j = 0; j < 16; j++) {
            atomicAdd(&psm[og*16 + j],      ysum[j]);
            atomicAdd(&psm[64 + og*16 + j], ysq[j]);
        }
    }
    __syncthreads();
    if (tid < 64) {
        atomicAdd(&g_sum[tid], psm[tid]);
        atomicAdd(&g_sq [tid], psm[64 + tid]);
    }
}

// ---------------------------------------------------------------------------
// Normalize + affine + ReLU, NHWC -> NCHW into d_out.
__global__ __launch_bounds__(1024) void k_norm_out(
    const float* __restrict__ gamma, const float* __restrict__ beta,
    float* __restrict__ out)
{
    __shared__ float t[32][33];
    int w0 = blockIdx.x * 32, c0 = blockIdx.y * 32;
    int bh = blockIdx.z;
    int b = bh / Hn, h = bh % Hn;
    int tx = threadIdx.x, ty = threadIdx.y;

    int c = c0 + tx;
    const float inv = 1.0f / (float)PIX;
    float mean = g_sum[c] * inv;
    float var  = g_sq[c] * inv - mean*mean;
    float rstd = rsqrtf(var + 1e-5f);
    float sc = gamma[c] * rstd;
    float sh = beta[c] - mean * sc;

    float v = g_y[((size_t)bh*Wn + (w0+ty))*Cn + c];
    t[ty][tx] = fmaxf(v*sc + sh, 0.f);
    __syncthreads();
    out[(((size_t)b*Cn + (c0+ty))*Hn + h)*Wn + (w0+tx)] = t[tx][ty];
}

// ---------------------------------------------------------------------------
extern "C" void kernel_launch(void* const* d_in, const int* in_sizes, int n_in,
                              void* d_out, int out_size)
{
    const float* x     = (const float*)d_in[0];
    const float* off_w = (const float*)d_in[1];
    const float* off_b = (const float*)d_in[2];
    const float* mod_w = (const float*)d_in[3];
    const float* mod_b = (const float*)d_in[4];
    const float* wmat  = (const float*)d_in[5];
    const float* bias  = (const float*)d_in[6];
    const float* gamma = (const float*)d_in[7];
    const float* beta  = (const float*)d_in[8];
    float* out = (float*)d_out;

    static int configured = 0;
    if (!configured) {
        cudaFuncSetAttribute(k_offmask, cudaFuncAttributeMaxDynamicSharedMemorySize, OFF_SMEM);
        cudaFuncSetAttribute(k_deform,  cudaFuncAttributeMaxDynamicSharedMemorySize, DEF_SMEM);
        configured = 1;
    }

    dim3 tgrid(Wn/32, Cn/32, Bn*Hn);
    dim3 tblk(32, 32);

    k_zero<<<1, 64>>>();
    k_wprep<<<64, 256>>>(wmat, off_w, mod_w);
    k_transpose_in<<<tgrid, tblk>>>(x);
    k_offmask<<<PIX/128, 128, OFF_SMEM>>>(off_b, mod_b);
    k_deform <<<PIX/128, 128, DEF_SMEM>>>(bias);
    k_norm_out<<<tgrid, tblk>>>(gamma, beta, out);
}

// round 5
// speedup vs baseline: 2.4906x; 1.6243x over previous
#include <cuda_runtime.h>
#include <cuda_bf16.h>
#include <math.h>
#include <cstdint>

#define Bn   8
#define Cn   64
#define Hn   128
#define Wn   128
#define PIX  (Bn*Hn*Wn)    // 131072

#define ASTR 72            // A smem stride in halves (bank = 4g+tc, conflict-free)
#define WSTR 72            // W smem stride in halves

// deform smem layout (bytes)
#define D_AH 0
#define D_AL (D_AH + 128*ASTR*2)        // 18432
#define D_WH (D_AL + 128*ASTR*2)        // 36864
#define D_WL (D_WH + 64*WSTR*2)         // 46080
#define D_PS (D_WL + 64*WSTR*2)         // 55296
#define DSM  (D_PS + 128*8*4)           // 59392

// offmask smem layout
#define O_AH 0
#define O_AL (O_AH + 128*ASTR*2)
#define O_WH (O_AL + 128*ASTR*2)
#define O_WL (O_WH + 32*WSTR*2)
#define OSM  (O_WL + 32*WSTR*2)         // 46080

// Scratch
__device__ float g_xt[PIX*Cn];            // x channels-last
__device__ float g_om[PIX*27];            // offsets+mask per pixel
__device__ float g_y [PIX*Cn];            // deform out [pix][c]
__device__ __nv_bfloat16 g_wdh[9*64*64];  // deform W hi   [tap][o][c]
__device__ __nv_bfloat16 g_wdl[9*64*64];  // deform W lo
__device__ __nv_bfloat16 g_woh[9*32*64];  // offmask W hi  [tap][o(32)][c]
__device__ __nv_bfloat16 g_wol[9*32*64];  // offmask W lo
__device__ float g_sum[Cn];
__device__ float g_sq [Cn];

// mma.sync m16n8k16 bf16 (family-common PTX, HMMA in SASS)
#define MMA16816(d0,d1,d2,d3,a0,a1,a2,a3,b0,b1) \
    asm volatile("mma.sync.aligned.m16n8k16.row.col.f32.bf16.bf16.f32 " \
        "{%0,%1,%2,%3}, {%4,%5,%6,%7}, {%8,%9}, {%0,%1,%2,%3};" \
        : "+f"(d0), "+f"(d1), "+f"(d2), "+f"(d3) \
        : "r"(a0), "r"(a1), "r"(a2), "r"(a3), "r"(b0), "r"(b1))

__device__ __forceinline__ uint32_t pkbf(__nv_bfloat16 a, __nv_bfloat16 b) {
    uint32_t r;
    asm("mov.b32 %0, {%1, %2};" : "=r"(r)
        : "h"(__bfloat16_as_ushort(a)), "h"(__bfloat16_as_ushort(b)));
    return r;
}
__device__ __forceinline__ void split4(float4 v, uint2& hi, uint2& lo) {
    __nv_bfloat16 hx = __float2bfloat16_rn(v.x), hy = __float2bfloat16_rn(v.y);
    __nv_bfloat16 hz = __float2bfloat16_rn(v.z), hw = __float2bfloat16_rn(v.w);
    hi.x = pkbf(hx, hy); hi.y = pkbf(hz, hw);
    __nv_bfloat16 lx = __float2bfloat16_rn(v.x - __bfloat162float(hx));
    __nv_bfloat16 ly = __float2bfloat16_rn(v.y - __bfloat162float(hy));
    __nv_bfloat16 lz = __float2bfloat16_rn(v.z - __bfloat162float(hz));
    __nv_bfloat16 lw = __float2bfloat16_rn(v.w - __bfloat162float(hw));
    lo.x = pkbf(lx, ly); lo.y = pkbf(lz, lw);
}

// ---------------------------------------------------------------------------
__global__ void k_zero() {
    int i = threadIdx.x;
    if (i < Cn) { g_sum[i] = 0.f; g_sq[i] = 0.f; }
}

// ---------------------------------------------------------------------------
// Weight prep: split to bf16 hi/lo, layout [tap][o][c] (c contiguous).
__global__ __launch_bounds__(256) void k_wprep(
    const float* __restrict__ wmat,
    const float* __restrict__ off_w, const float* __restrict__ mod_w)
{
    for (int i = blockIdx.x*256 + threadIdx.x; i < 9*4096 + 9*2048; i += gridDim.x*256) {
        if (i < 9*4096) {
            int tap = i >> 12, r = i & 4095;
            int o = r >> 6, c = r & 63;
            float v = wmat[(o*64 + c)*9 + tap];
            __nv_bfloat16 h = __float2bfloat16_rn(v);
            __nv_bfloat16 l = __float2bfloat16_rn(v - __bfloat162float(h));
            g_wdh[i] = h; g_wdl[i] = l;
        } else {
            int j = i - 9*4096;
            int tap = j >> 11, r = j & 2047;
            int o = r >> 6, c = r & 63;
            float v = 0.f;
            if (o < 18)      v = off_w[(o*64 + c)*9 + tap];
            else if (o < 27) v = mod_w[((o-18)*64 + c)*9 + tap];
            __nv_bfloat16 h = __float2bfloat16_rn(v);
            __nv_bfloat16 l = __float2bfloat16_rn(v - __bfloat162float(h));
            g_woh[j] = h; g_wol[j] = l;
        }
    }
}

// ---------------------------------------------------------------------------
// x[b][c][h][w] -> g_xt[((b*H+h)*W+w)*C + c]
__global__ __launch_bounds__(1024) void k_transpose_in(const float* __restrict__ x) {
    __shared__ float t[32][33];
    int w0 = blockIdx.x * 32, c0 = blockIdx.y * 32;
    int bh = blockIdx.z;
    int b = bh / Hn, h = bh % Hn;
    int tx = threadIdx.x, ty = threadIdx.y;
    t[ty][tx] = x[(((b*Cn) + (c0+ty))*Hn + h)*Wn + (w0+tx)];
    __syncthreads();
    g_xt[((size_t)bh*Wn + (w0+ty))*Cn + (c0+tx)] = t[tx][ty];
}

// ---------------------------------------------------------------------------
// offset/mask conv on HMMA: per tap, stage shifted A (hi/lo) + W (hi/lo),
// 3-term split mma accumulation. Block = 1 row (128 px), 4 warps.
__global__ __launch_bounds__(128) void k_offmask(
    const float* __restrict__ off_b, const float* __restrict__ mod_b)
{
    extern __shared__ __align__(16) char sm[];
    __nv_bfloat16* aH = (__nv_bfloat16*)(sm + O_AH);
    __nv_bfloat16* aL = (__nv_bfloat16*)(sm + O_AL);
    __nv_bfloat16* wH = (__nv_bfloat16*)(sm + O_WH);
    __nv_bfloat16* wL = (__nv_bfloat16*)(sm + O_WL);

    int tid = threadIdx.x;
    int wid = tid >> 5, lane = tid & 31;
    int g = lane >> 2, tc = lane & 3;
    int blk = blockIdx.x;
    int b = blk >> 7, h = blk & 127;
    int p0 = blk * 128;
    int c4 = tid & 15, grp = tid >> 4;

    float dacc[2][4][4];
    #pragma unroll
    for (int m = 0; m < 2; m++)
        #pragma unroll
        for (int n = 0; n < 4; n++)
            #pragma unroll
            for (int q = 0; q < 4; q++) dacc[m][n][q] = 0.f;

    for (int tap = 0; tap < 9; tap++) {
        __syncthreads();
        // stage W hi/lo with pad stride
        for (int i = tid; i < 256; i += 128) {
            int row = i >> 3, q = i & 7;
            *(uint4*)((char*)wH + row*(WSTR*2) + q*16) = ((const uint4*)&g_woh[tap*2048])[i];
            *(uint4*)((char*)wL + row*(WSTR*2) + q*16) = ((const uint4*)&g_wol[tap*2048])[i];
        }
        // stage A: shifted x row -> bf16 hi/lo
        int y = h + tap/3 - 1;
        int dxs = tap%3 - 1;
        #pragma unroll 4
        for (int it = 0; it < 16; it++) {
            int px = it*8 + grp;
            int xx = px + dxs;
            float4 v = make_float4(0.f,0.f,0.f,0.f);
            if (y >= 0 && y < Hn && xx >= 0 && xx < Wn)
                v = *(const float4*)&g_xt[(((size_t)b*Hn + y)*Wn + xx)*Cn + c4*4];
            uint2 hi, lo; split4(v, hi, lo);
            *(uint2*)((char*)aH + px*(ASTR*2) + c4*8) = hi;
            *(uint2*)((char*)aL + px*(ASTR*2) + c4*8) = lo;
        }
        __syncthreads();
        // MMA: warp owns px [wid*32, wid*32+32)
        #pragma unroll
        for (int ks = 0; ks < 4; ks++) {
            int kb = ks*16 + 2*tc;
            uint32_t ah[2][4], al[2][4];
            #pragma unroll
            for (int m = 0; m < 2; m++) {
                int r0 = wid*32 + m*16 + g;
                ah[m][0] = *(const uint32_t*)&aH[(r0   )*ASTR + kb];
                ah[m][1] = *(const uint32_t*)&aH[(r0+8 )*ASTR + kb];
                ah[m][2] = *(const uint32_t*)&aH[(r0   )*ASTR + kb + 8];
                ah[m][3] = *(const uint32_t*)&aH[(r0+8 )*ASTR + kb + 8];
                al[m][0] = *(const uint32_t*)&aL[(r0   )*ASTR + kb];
                al[m][1] = *(const uint32_t*)&aL[(r0+8 )*ASTR + kb];
                al[m][2] = *(const uint32_t*)&aL[(r0   )*ASTR + kb + 8];
                al[m][3] = *(const uint32_t*)&aL[(r0+8 )*ASTR + kb + 8];
            }
            #pragma unroll
            for (int n = 0; n < 4; n++) {
                int nr = n*8 + g;
                uint32_t bh0 = *(const uint32_t*)&wH[nr*WSTR + kb];
                uint32_t bh1 = *(const uint32_t*)&wH[nr*WSTR + kb + 8];
                uint32_t bl0 = *(const uint32_t*)&wL[nr*WSTR + kb];
                uint32_t bl1 = *(const uint32_t*)&wL[nr*WSTR + kb + 8];
                #pragma unroll
                for (int m = 0; m < 2; m++) {
                    MMA16816(dacc[m][n][0],dacc[m][n][1],dacc[m][n][2],dacc[m][n][3],
                             ah[m][0],ah[m][1],ah[m][2],ah[m][3], bh0,bh1);
                    MMA16816(dacc[m][n][0],dacc[m][n][1],dacc[m][n][2],dacc[m][n][3],
                             al[m][0],al[m][1],al[m][2],al[m][3], bh0,bh1);
                    MMA16816(dacc[m][n][0],dacc[m][n][1],dacc[m][n][2],dacc[m][n][3],
                             ah[m][0],ah[m][1],ah[m][2],ah[m][3], bl0,bl1);
                }
            }
        }
    }

    // epilogue: bias + sigmoid, write g_om[px][27]
    #pragma unroll
    for (int m = 0; m < 2; m++) {
        int px = p0 + wid*32 + m*16 + g;
        #pragma unroll
        for (int n = 0; n < 4; n++) {
            int o = n*8 + 2*tc;
            #pragma unroll
            for (int j = 0; j < 2; j++) {
                int oo = o + j;
                if (oo >= 27) continue;
                float v0 = dacc[m][n][j], v1 = dacc[m][n][2+j];
                if (oo < 18) { v0 += off_b[oo]; v1 += off_b[oo]; }
                else {
                    v0 = 2.0f / (1.0f + expf(-(v0 + mod_b[oo-18])));
                    v1 = 2.0f / (1.0f + expf(-(v1 + mod_b[oo-18])));
                }
                g_om[(size_t)px*27 + oo]     = v0;
                g_om[(size_t)(px+8)*27 + oo] = v1;
            }
        }
    }
}

// ---------------------------------------------------------------------------
// Deformable conv on HMMA: params -> cooperative bilinear gather -> bf16
// split A -> 3-term mma accumulation over 9 taps. Block = 128 px, 4 warps.
__global__ __launch_bounds__(128) void k_deform(const float* __restrict__ bias)
{
    extern __shared__ __align__(16) char sm[];
    __nv_bfloat16* aH = (__nv_bfloat16*)(sm + D_AH);
    __nv_bfloat16* aL = (__nv_bfloat16*)(sm + D_AL);
    __nv_bfloat16* wH = (__nv_bfloat16*)(sm + D_WH);
    __nv_bfloat16* wL = (__nv_bfloat16*)(sm + D_WL);
    float* psm = (float*)(sm + D_PS);

    int tid = threadIdx.x;
    int wid = tid >> 5, lane = tid & 31;
    int g = lane >> 2, tc = lane & 3;
    int blk = blockIdx.x;
    int b = blk >> 7, h = blk & 127;
    int p0 = blk * 128;
    int c4 = tid & 15, grp = tid >> 4;

    float dacc[2][8][4];
    #pragma unroll
    for (int m = 0; m < 2; m++)
        #pragma unroll
        for (int n = 0; n < 8; n++)
            #pragma unroll
            for (int q = 0; q < 4; q++) dacc[m][n][q] = 0.f;

    for (int tap = 0; tap < 9; tap++) {
        __syncthreads();
        // stage W hi/lo
        for (int i = tid; i < 512; i += 128) {
            int row = i >> 3, q = i & 7;
            *(uint4*)((char*)wH + row*(WSTR*2) + q*16) = ((const uint4*)&g_wdh[tap*4096])[i];
            *(uint4*)((char*)wL + row*(WSTR*2) + q*16) = ((const uint4*)&g_wdl[tap*4096])[i];
        }
        // bilinear params: thread = pixel
        {
            const float* omp = &g_om[(size_t)(p0 + tid)*27];
            float dy = omp[tap*2], dx = omp[tap*2+1], mk = omp[18+tap];
            float py = (float)(h + tap/3 - 1) + dy;
            float px_ = (float)(tid + tap%3 - 1) + dx;
            float fy = floorf(py), fx = floorf(px_);
            float ly = py - fy,    lx = px_ - fx;
            int y0 = (int)fy, x0 = (int)fx;
            int y1 = y0 + 1,  x1 = x0 + 1;
            float vy0 = (y0 >= 0 && y0 < Hn) ? 1.f : 0.f;
            float vy1 = (y1 >= 0 && y1 < Hn) ? 1.f : 0.f;
            float vx0 = (x0 >= 0 && x0 < Wn) ? 1.f : 0.f;
            float vx1 = (x1 >= 0 && x1 < Wn) ? 1.f : 0.f;
            int iy0 = min(max(y0,0),Hn-1), iy1 = min(max(y1,0),Hn-1);
            int ix0 = min(max(x0,0),Wn-1), ix1 = min(max(x1,0),Wn-1);
            int base = (b*Hn)*Wn;
            psm[tid*8+0] = (1.f-ly)*(1.f-lx)*mk * vy0*vx0;
            psm[tid*8+1] = (1.f-ly)*lx      *mk * vy0*vx1;
            psm[tid*8+2] = ly      *(1.f-lx)*mk * vy1*vx0;
            psm[tid*8+3] = ly      *lx      *mk * vy1*vx1;
            psm[tid*8+4] = __int_as_float(((base + iy0*Wn + ix0)*Cn) >> 2);
            psm[tid*8+5] = __int_as_float(((base + iy0*Wn + ix1)*Cn) >> 2);
            psm[tid*8+6] = __int_as_float(((base + iy1*Wn + ix0)*Cn) >> 2);
            psm[tid*8+7] = __int_as_float(((base + iy1*Wn + ix1)*Cn) >> 2);
        }
        __syncthreads();
        // gather + blend + split: lane c4 handles 4 channels of 16 pixels
        {
            const float4* P = (const float4*)g_xt;
            #pragma unroll 2
            for (int it = 0; it < 16; it++) {
                int px = it*8 + grp;
                float w00 = psm[px*8+0], w01 = psm[px*8+1];
                float w10 = psm[px*8+2], w11 = psm[px*8+3];
                int i00 = __float_as_int(psm[px*8+4]);
                int i01 = __float_as_int(psm[px*8+5]);
                int i10 = __float_as_int(psm[px*8+6]);
                int i11 = __float_as_int(psm[px*8+7]);
                float4 a = P[i00 + c4], e = P[i01 + c4];
                float4 c = P[i10 + c4], d = P[i11 + c4];
                float4 v;
                v.x = w00*a.x + w01*e.x + w10*c.x + w11*d.x;
                v.y = w00*a.y + w01*e.y + w10*c.y + w11*d.y;
                v.z = w00*a.z + w01*e.z + w10*c.z + w11*d.z;
                v.w = w00*a.w + w01*e.w + w10*c.w + w11*d.w;
                uint2 hi, lo; split4(v, hi, lo);
                *(uint2*)((char*)aH + px*(ASTR*2) + c4*8) = hi;
                *(uint2*)((char*)aL + px*(ASTR*2) + c4*8) = lo;
            }
        }
        __syncthreads();
        // MMA: warp owns px [wid*32, wid*32+32), N=64
        #pragma unroll
        for (int ks = 0; ks < 4; ks++) {
            int kb = ks*16 + 2*tc;
            uint32_t ah[2][4], al[2][4];
            #pragma unroll
            for (int m = 0; m < 2; m++) {
                int r0 = wid*32 + m*16 + g;
                ah[m][0] = *(const uint32_t*)&aH[(r0   )*ASTR + kb];
                ah[m][1] = *(const uint32_t*)&aH[(r0+8 )*ASTR + kb];
                ah[m][2] = *(const uint32_t*)&aH[(r0   )*ASTR + kb + 8];
                ah[m][3] = *(const uint32_t*)&aH[(r0+8 )*ASTR + kb + 8];
                al[m][0] = *(const uint32_t*)&aL[(r0   )*ASTR + kb];
                al[m][1] = *(const uint32_t*)&aL[(r0+8 )*ASTR + kb];
                al[m][2] = *(const uint32_t*)&aL[(r0   )*ASTR + kb + 8];
                al[m][3] = *(const uint32_t*)&aL[(r0+8 )*ASTR + kb + 8];
            }
            #pragma unroll
            for (int n = 0; n < 8; n++) {
                int nr = n*8 + g;
                uint32_t bh0 = *(const uint32_t*)&wH[nr*WSTR + kb];
                uint32_t bh1 = *(const uint32_t*)&wH[nr*WSTR + kb + 8];
                uint32_t bl0 = *(const uint32_t*)&wL[nr*WSTR + kb];
                uint32_t bl1 = *(const uint32_t*)&wL[nr*WSTR + kb + 8];
                #pragma unroll
                for (int m = 0; m < 2; m++) {
                    MMA16816(dacc[m][n][0],dacc[m][n][1],dacc[m][n][2],dacc[m][n][3],
                             ah[m][0],ah[m][1],ah[m][2],ah[m][3], bh0,bh1);
                    MMA16816(dacc[m][n][0],dacc[m][n][1],dacc[m][n][2],dacc[m][n][3],
                             al[m][0],al[m][1],al[m][2],al[m][3], bh0,bh1);
                    MMA16816(dacc[m][n][0],dacc[m][n][1],dacc[m][n][2],dacc[m][n][3],
                             ah[m][0],ah[m][1],ah[m][2],ah[m][3], bl0,bl1);
                }
            }
        }
    }

    // epilogue: +bias, store g_y[px][64]
    #pragma unroll
    for (int m = 0; m < 2; m++) {
        int px = p0 + wid*32 + m*16 + g;
        #pragma unroll
        for (int n = 0; n < 8; n++) {
            int o = n*8 + 2*tc;
            float b0 = bias[o], b1 = bias[o+1];
            float2 v0 = make_float2(dacc[m][n][0] + b0, dacc[m][n][1] + b1);
            float2 v1 = make_float2(dacc[m][n][2] + b0, dacc[m][n][3] + b1);
            *(float2*)&g_y[(size_t)px*64 + o]     = v0;
            *(float2*)&g_y[(size_t)(px+8)*64 + o] = v1;
        }
    }
}

// ---------------------------------------------------------------------------
// Per-channel sum/sumsq over g_y (streaming).
__global__ __launch_bounds__(256) void k_stats() {
    __shared__ float ss[Cn], sq[Cn];
    int tid = threadIdx.x;
    if (tid < Cn) { ss[tid] = 0.f; sq[tid] = 0.f; }
    __syncthreads();
    int c4 = tid & 15, pxg = tid >> 4;
    float4 s = make_float4(0,0,0,0), q = make_float4(0,0,0,0);
    for (int it = 0; it < 32; it++) {
        size_t px = (size_t)blockIdx.x*512 + it*16 + pxg;
        float4 v = *(const float4*)&g_y[px*64 + c4*4];
        s.x += v.x; s.y += v.y; s.z += v.z; s.w += v.w;
        q.x += v.x*v.x; q.y += v.y*v.y; q.z += v.z*v.z; q.w += v.w*v.w;
    }
    atomicAdd(&ss[c4*4+0], s.x); atomicAdd(&ss[c4*4+1], s.y);
    atomicAdd(&ss[c4*4+2], s.z); atomicAdd(&ss[c4*4+3], s.w);
    atomicAdd(&sq[c4*4+0], q.x); atomicAdd(&sq[c4*4+1], q.y);
    atomicAdd(&sq[c4*4+2], q.z); atomicAdd(&sq[c4*4+3], q.w);
    __syncthreads();
    if (tid < Cn) { atomicAdd(&g_sum[tid], ss[tid]); atomicAdd(&g_sq[tid], sq[tid]); }
}

// ---------------------------------------------------------------------------
// Normalize + affine + ReLU, NHWC -> NCHW into d_out.
__global__ __launch_bounds__(1024) void k_norm_out(
    const float* __restrict__ gamma, const float* __restrict__ beta,
    float* __restrict__ out)
{
    __shared__ float t[32][33];
    int w0 = blockIdx.x * 32, c0 = blockIdx.y * 32;
    int bh = blockIdx.z;
    int b = bh / Hn, h = bh % Hn;
    int tx = threadIdx.x, ty = threadIdx.y;

    int c = c0 + tx;
    const float inv = 1.0f / (float)PIX;
    float mean = g_sum[c] * inv;
    float var  = g_sq[c] * inv - mean*mean;
    float rstd = rsqrtf(var + 1e-5f);
    float sc = gamma[c] * rstd;
    float sh = beta[c] - mean * sc;

    float v = g_y[((size_t)bh*Wn + (w0+ty))*Cn + c];
    t[ty][tx] = fmaxf(v*sc + sh, 0.f);
    __syncthreads();
    out[(((size_t)b*Cn + (c0+ty))*Hn + h)*Wn + (w0+tx)] = t[tx][ty];
}

// ---------------------------------------------------------------------------
extern "C" void kernel_launch(void* const* d_in, const int* in_sizes, int n_in,
                              void* d_out, int out_size)
{
    const float* x     = (const float*)d_in[0];
    const float* off_w = (const float*)d_in[1];
    const float* off_b = (const float*)d_in[2];
    const float* mod_w = (const float*)d_in[3];
    const float* mod_b = (const float*)d_in[4];
    const float* wmat  = (const float*)d_in[5];
    const float* bias  = (const float*)d_in[6];
    const float* gamma = (const float*)d_in[7];
    const float* beta  = (const float*)d_in[8];
    float* out = (float*)d_out;

    static int configured = 0;
    if (!configured) {
        cudaFuncSetAttribute(k_offmask, cudaFuncAttributeMaxDynamicSharedMemorySize, OSM);
        cudaFuncSetAttribute(k_deform,  cudaFuncAttributeMaxDynamicSharedMemorySize, DSM);
        configured = 1;
    }

    dim3 tgrid(Wn/32, Cn/32, Bn*Hn);
    dim3 tblk(32, 32);

    k_zero<<<1, 64>>>();
    k_wprep<<<64, 256>>>(wmat, off_w, mod_w);
    k_transpose_in<<<tgrid, tblk>>>(x);
    k_offmask<<<PIX/128, 128, OSM>>>(off_b, mod_b);
    k_deform <<<PIX/128, 128, DSM>>>(bias);
    k_stats  <<<PIX/512, 256>>>();
    k_norm_out<<<tgrid, tblk>>>(gamma, beta, out);
}

// round 6
// speedup vs baseline: 2.9331x; 1.1777x over previous
#include <cuda_runtime.h>
#include <cuda_bf16.h>
#include <math.h>
#include <cstdint>

#define Bn   8
#define Cn   64
#define Hn   128
#define Wn   128
#define PIX  (Bn*Hn*Wn)    // 131072

// deform smem (bytes): aH 16384 | aL 16384 | wH 8192 | wL 8192 | psm 4096
#define D_AL 16384
#define D_WH 32768
#define D_WL 40960
#define D_PS 49152
#define DSM  53248
// offmask smem: aH 16384 | aL 16384 | wH 4096 | wL 4096
#define O_AL 16384
#define O_WH 32768
#define O_WL 36864
#define OSM  40960

// Scratch
__device__ float g_xt[PIX*Cn];            // x channels-last
__device__ float g_om[PIX*27];            // offsets+mask per pixel
__device__ float g_y [PIX*Cn];            // deform out [pix][c]
__device__ __nv_bfloat16 g_wdh[9*64*64];  // deform W hi   [tap][o][c]
__device__ __nv_bfloat16 g_wdl[9*64*64];  // deform W lo
__device__ __nv_bfloat16 g_woh[9*32*64];  // offmask W hi  [tap][o(32)][c]
__device__ __nv_bfloat16 g_wol[9*32*64];  // offmask W lo
__device__ float g_sum[Cn];
__device__ float g_sq [Cn];

#define MMA16816(d0,d1,d2,d3,a0,a1,a2,a3,b0,b1) \
    asm volatile("mma.sync.aligned.m16n8k16.row.col.f32.bf16.bf16.f32 " \
        "{%0,%1,%2,%3}, {%4,%5,%6,%7}, {%8,%9}, {%0,%1,%2,%3};" \
        : "+f"(d0), "+f"(d1), "+f"(d2), "+f"(d3) \
        : "r"(a0), "r"(a1), "r"(a2), "r"(a3), "r"(b0), "r"(b1))

#define LDSM4(r0,r1,r2,r3,a) \
    asm volatile("ldmatrix.sync.aligned.m8n8.x4.shared.b16 {%0,%1,%2,%3}, [%4];" \
        : "=r"(r0), "=r"(r1), "=r"(r2), "=r"(r3) : "r"(a))

__device__ __forceinline__ uint32_t lds_addr(const void* p) {
    return (uint32_t)__cvta_generic_to_shared(p);
}
__device__ __forceinline__ uint32_t pkbf(__nv_bfloat16 a, __nv_bfloat16 b) {
    uint32_t r;
    asm("mov.b32 %0, {%1, %2};" : "=r"(r)
        : "h"(__bfloat16_as_ushort(a)), "h"(__bfloat16_as_ushort(b)));
    return r;
}
__device__ __forceinline__ void split4(float4 v, uint2& hi, uint2& lo) {
    __nv_bfloat16 hx = __float2bfloat16_rn(v.x), hy = __float2bfloat16_rn(v.y);
    __nv_bfloat16 hz = __float2bfloat16_rn(v.z), hw = __float2bfloat16_rn(v.w);
    hi.x = pkbf(hx, hy); hi.y = pkbf(hz, hw);
    __nv_bfloat16 lx = __float2bfloat16_rn(v.x - __bfloat162float(hx));
    __nv_bfloat16 ly = __float2bfloat16_rn(v.y - __bfloat162float(hy));
    __nv_bfloat16 lz = __float2bfloat16_rn(v.z - __bfloat162float(hz));
    __nv_bfloat16 lw = __float2bfloat16_rn(v.w - __bfloat162float(hw));
    lo.x = pkbf(lx, ly); lo.y = pkbf(lz, lw);
}

// ---------------------------------------------------------------------------
__global__ void k_zero() {
    int i = threadIdx.x;
    if (i < Cn) { g_sum[i] = 0.f; g_sq[i] = 0.f; }
}

// ---------------------------------------------------------------------------
__global__ __launch_bounds__(256) void k_wprep(
    const float* __restrict__ wmat,
    const float* __restrict__ off_w, const float* __restrict__ mod_w)
{
    for (int i = blockIdx.x*256 + threadIdx.x; i < 9*4096 + 9*2048; i += gridDim.x*256) {
        if (i < 9*4096) {
            int tap = i >> 12, r = i & 4095;
            int o = r >> 6, c = r & 63;
            float v = wmat[(o*64 + c)*9 + tap];
            __nv_bfloat16 h = __float2bfloat16_rn(v);
            __nv_bfloat16 l = __float2bfloat16_rn(v - __bfloat162float(h));
            g_wdh[i] = h; g_wdl[i] = l;
        } else {
            int j = i - 9*4096;
            int tap = j >> 11, r = j & 2047;
            int o = r >> 6, c = r & 63;
            float v = 0.f;
            if (o < 18)      v = off_w[(o*64 + c)*9 + tap];
            else if (o < 27) v = mod_w[((o-18)*64 + c)*9 + tap];
            __nv_bfloat16 h = __float2bfloat16_rn(v);
            __nv_bfloat16 l = __float2bfloat16_rn(v - __bfloat162float(h));
            g_woh[j] = h; g_wol[j] = l;
        }
    }
}

// ---------------------------------------------------------------------------
__global__ __launch_bounds__(1024) void k_transpose_in(const float* __restrict__ x) {
    __shared__ float t[32][33];
    int w0 = blockIdx.x * 32, c0 = blockIdx.y * 32;
    int bh = blockIdx.z;
    int b = bh / Hn, h = bh % Hn;
    int tx = threadIdx.x, ty = threadIdx.y;
    t[ty][tx] = x[(((b*Cn) + (c0+ty))*Hn + h)*Wn + (w0+tx)];
    __syncthreads();
    g_xt[((size_t)bh*Wn + (w0+ty))*Cn + (c0+tx)] = t[tx][ty];
}

// ---------------------------------------------------------------------------
// offset/mask conv, HMMA + ldmatrix + XOR-swizzled smem. 256 thr, 8 warps,
// 16 px/warp, N=32 (27 used), 3-term bf16 split.
__global__ __launch_bounds__(256) void k_offmask(
    const float* __restrict__ off_b, const float* __restrict__ mod_b)
{
    extern __shared__ __align__(16) char sm[];
    char* aH = sm;          char* aL = sm + O_AL;
    char* wH = sm + O_WH;   char* wL = sm + O_WL;
    uint32_t aHb = lds_addr(aH), aLb = lds_addr(aL);
    uint32_t wHb = lds_addr(wH), wLb = lds_addr(wL);

    int tid = threadIdx.x;
    int wid = tid >> 5, lane = tid & 31;
    int g = lane >> 2, tc = lane & 3;
    int lrow = lane & 7, lmat = lane >> 3;
    int blk = blockIdx.x;
    int b = blk >> 7, h = blk & 127;
    int p0 = blk * 128;
    int c4 = tid & 15, grp = tid >> 4;

    float dacc[4][4];
    #pragma unroll
    for (int n = 0; n < 4; n++)
        #pragma unroll
        for (int q = 0; q < 4; q++) dacc[n][q] = 0.f;

    // ldmatrix address precompute
    int arow = wid*16 + ((lmat & 1) << 3) + lrow;
    uint32_t aRowOff = arow*128;
    int asw  = (arow & 7) << 4;
    int acol = (lmat >> 1) << 4;
    int browb = ((lmat >> 1) << 3) + lrow;
    int bsw  = (browb & 7) << 4;
    int bcol = (lmat & 1) << 4;

    for (int tap = 0; tap < 9; tap++) {
        __syncthreads();
        // stage W (32 rows x 128B), swizzled
        for (int i = tid; i < 256; i += 256) {
            int row = i >> 3, q = i & 7;
            int off = row*128 + ((q*16) ^ ((row & 7)*16));
            *(uint4*)(wH + off) = ((const uint4*)&g_woh[tap*2048])[i];
            *(uint4*)(wL + off) = ((const uint4*)&g_wol[tap*2048])[i];
        }
        // stage A: shifted x row -> bf16 hi/lo, swizzled
        int y = h + tap/3 - 1;
        int dxs = tap%3 - 1;
        #pragma unroll 4
        for (int it = 0; it < 8; it++) {
            int px = it*16 + grp;
            int xx = px + dxs;
            float4 v = make_float4(0.f,0.f,0.f,0.f);
            if (y >= 0 && y < Hn && xx >= 0 && xx < Wn)
                v = *(const float4*)&g_xt[(((size_t)b*Hn + y)*Wn + xx)*Cn + c4*4];
            uint2 hi, lo; split4(v, hi, lo);
            int off = px*128 + ((c4*8) ^ ((px & 7)*16));
            *(uint2*)(aH + off) = hi;
            *(uint2*)(aL + off) = lo;
        }
        __syncthreads();
        #pragma unroll
        for (int ks = 0; ks < 4; ks++) {
            uint32_t aoff = aRowOff + ((acol + ks*32) ^ asw);
            uint32_t ah0,ah1,ah2,ah3, al0,al1,al2,al3;
            LDSM4(ah0,ah1,ah2,ah3, aHb + aoff);
            LDSM4(al0,al1,al2,al3, aLb + aoff);
            #pragma unroll
            for (int np = 0; np < 2; np++) {
                uint32_t boff = (np*16 + browb)*128 + ((bcol + ks*32) ^ bsw);
                uint32_t bh0,bh1,bh2,bh3, bl0,bl1,bl2,bl3;
                LDSM4(bh0,bh1,bh2,bh3, wHb + boff);
                LDSM4(bl0,bl1,bl2,bl3, wLb + boff);
                MMA16816(dacc[2*np][0],dacc[2*np][1],dacc[2*np][2],dacc[2*np][3],
                         ah0,ah1,ah2,ah3, bh0,bh1);
                MMA16816(dacc[2*np][0],dacc[2*np][1],dacc[2*np][2],dacc[2*np][3],
                         al0,al1,al2,al3, bh0,bh1);
                MMA16816(dacc[2*np][0],dacc[2*np][1],dacc[2*np][2],dacc[2*np][3],
                         ah0,ah1,ah2,ah3, bl0,bl1);
                MMA16816(dacc[2*np+1][0],dacc[2*np+1][1],dacc[2*np+1][2],dacc[2*np+1][3],
                         ah0,ah1,ah2,ah3, bh2,bh3);
                MMA16816(dacc[2*np+1][0],dacc[2*np+1][1],dacc[2*np+1][2],dacc[2*np+1][3],
                         al0,al1,al2,al3, bh2,bh3);
                MMA16816(dacc[2*np+1][0],dacc[2*np+1][1],dacc[2*np+1][2],dacc[2*np+1][3],
                         ah0,ah1,ah2,ah3, bl2,bl3);
            }
        }
    }

    // epilogue
    int px = p0 + wid*16 + g;
    #pragma unroll
    for (int nt = 0; nt < 4; nt++) {
        int o = nt*8 + 2*tc;
        if (o < 27) {
            float v0 = dacc[nt][0], v2 = dacc[nt][2];
            if (o < 18) { v0 += off_b[o]; v2 += off_b[o]; }
            else {
                v0 = 2.0f / (1.0f + expf(-(v0 + mod_b[o-18])));
                v2 = 2.0f / (1.0f + expf(-(v2 + mod_b[o-18])));
            }
            g_om[(size_t)px*27 + o]     = v0;
            g_om[(size_t)(px+8)*27 + o] = v2;
        }
        if (o+1 < 27) {
            float v1 = dacc[nt][1], v3 = dacc[nt][3];
            if (o+1 < 18) { v1 += off_b[o+1]; v3 += off_b[o+1]; }
            else {
                v1 = 2.0f / (1.0f + expf(-(v1 + mod_b[o+1-18])));
                v3 = 2.0f / (1.0f + expf(-(v3 + mod_b[o+1-18])));
            }
            g_om[(size_t)px*27 + o+1]     = v1;
            g_om[(size_t)(px+8)*27 + o+1] = v3;
        }
    }
}

// ---------------------------------------------------------------------------
// Deformable conv, HMMA + ldmatrix + swizzle, fused BN stats. 256 thr.
__global__ __launch_bounds__(256) void k_deform(const float* __restrict__ bias)
{
    extern __shared__ __align__(16) char sm[];
    char* aH = sm;          char* aL = sm + D_AL;
    char* wH = sm + D_WH;   char* wL = sm + D_WL;
    float* psm = (float*)(sm + D_PS);
    uint32_t aHb = lds_addr(aH), aLb = lds_addr(aL);
    uint32_t wHb = lds_addr(wH), wLb = lds_addr(wL);

    int tid = threadIdx.x;
    int wid = tid >> 5, lane = tid & 31;
    int g = lane >> 2, tc = lane & 3;
    int lrow = lane & 7, lmat = lane >> 3;
    int blk = blockIdx.x;
    int b = blk >> 7, h = blk & 127;
    int p0 = blk * 128;
    int c4 = tid & 15, grp = tid >> 4;

    float dacc[8][4];
    #pragma unroll
    for (int n = 0; n < 8; n++)
        #pragma unroll
        for (int q = 0; q < 4; q++) dacc[n][q] = 0.f;

    int arow = wid*16 + ((lmat & 1) << 3) + lrow;
    uint32_t aRowOff = arow*128;
    int asw  = (arow & 7) << 4;
    int acol = (lmat >> 1) << 4;
    int browb = ((lmat >> 1) << 3) + lrow;
    int bsw  = (browb & 7) << 4;
    int bcol = (lmat & 1) << 4;

    for (int tap = 0; tap < 9; tap++) {
        __syncthreads();
        // stage W (64 rows x 128B)
        for (int i = tid; i < 512; i += 256) {
            int row = i >> 3, q = i & 7;
            int off = row*128 + ((q*16) ^ ((row & 7)*16));
            *(uint4*)(wH + off) = ((const uint4*)&g_wdh[tap*4096])[i];
            *(uint4*)(wL + off) = ((const uint4*)&g_wdl[tap*4096])[i];
        }
        // bilinear params (threads 0..127, one pixel each)
        if (tid < 128) {
            const float* omp = &g_om[(size_t)(p0 + tid)*27];
            float dy = omp[tap*2], dx = omp[tap*2+1], mk = omp[18+tap];
            float py = (float)(h + tap/3 - 1) + dy;
            float px_ = (float)(tid + tap%3 - 1) + dx;
            float fy = floorf(py), fx = floorf(px_);
            float ly = py - fy,    lx = px_ - fx;
            int y0 = (int)fy, x0 = (int)fx;
            int y1 = y0 + 1,  x1 = x0 + 1;
            float vy0 = (y0 >= 0 && y0 < Hn) ? 1.f : 0.f;
            float vy1 = (y1 >= 0 && y1 < Hn) ? 1.f : 0.f;
            float vx0 = (x0 >= 0 && x0 < Wn) ? 1.f : 0.f;
            float vx1 = (x1 >= 0 && x1 < Wn) ? 1.f : 0.f;
            int iy0 = min(max(y0,0),Hn-1), iy1 = min(max(y1,0),Hn-1);
            int ix0 = min(max(x0,0),Wn-1), ix1 = min(max(x1,0),Wn-1);
            int base = (b*Hn)*Wn;
            psm[tid*8+0] = (1.f-ly)*(1.f-lx)*mk * vy0*vx0;
            psm[tid*8+1] = (1.f-ly)*lx      *mk * vy0*vx1;
            psm[tid*8+2] = ly      *(1.f-lx)*mk * vy1*vx0;
            psm[tid*8+3] = ly      *lx      *mk * vy1*vx1;
            psm[tid*8+4] = __int_as_float(((base + iy0*Wn + ix0)*Cn) >> 2);
            psm[tid*8+5] = __int_as_float(((base + iy0*Wn + ix1)*Cn) >> 2);
            psm[tid*8+6] = __int_as_float(((base + iy1*Wn + ix0)*Cn) >> 2);
            psm[tid*8+7] = __int_as_float(((base + iy1*Wn + ix1)*Cn) >> 2);
        }
        __syncthreads();
        // cooperative gather + blend + split (16 lanes/px)
        {
            const float4* P = (const float4*)g_xt;
            #pragma unroll 2
            for (int it = 0; it < 8; it++) {
                int px = it*16 + grp;
                float w00 = psm[px*8+0], w01 = psm[px*8+1];
                float w10 = psm[px*8+2], w11 = psm[px*8+3];
                int i00 = __float_as_int(psm[px*8+4]);
                int i01 = __float_as_int(psm[px*8+5]);
                int i10 = __float_as_int(psm[px*8+6]);
                int i11 = __float_as_int(psm[px*8+7]);
                float4 a = P[i00 + c4], e = P[i01 + c4];
                float4 c = P[i10 + c4], d = P[i11 + c4];
                float4 v;
                v.x = w00*a.x + w01*e.x + w10*c.x + w11*d.x;
                v.y = w00*a.y + w01*e.y + w10*c.y + w11*d.y;
                v.z = w00*a.z + w01*e.z + w10*c.z + w11*d.z;
                v.w = w00*a.w + w01*e.w + w10*c.w + w11*d.w;
                uint2 hi, lo; split4(v, hi, lo);
                int off = px*128 + ((c4*8) ^ ((px & 7)*16));
                *(uint2*)(aH + off) = hi;
                *(uint2*)(aL + off) = lo;
            }
        }
        __syncthreads();
        #pragma unroll
        for (int ks = 0; ks < 4; ks++) {
            uint32_t aoff = aRowOff + ((acol + ks*32) ^ asw);
            uint32_t ah0,ah1,ah2,ah3, al0,al1,al2,al3;
            LDSM4(ah0,ah1,ah2,ah3, aHb + aoff);
            LDSM4(al0,al1,al2,al3, aLb + aoff);
            #pragma unroll
            for (int np = 0; np < 4; np++) {
                uint32_t boff = (np*16 + browb)*128 + ((bcol + ks*32) ^ bsw);
                uint32_t bh0,bh1,bh2,bh3, bl0,bl1,bl2,bl3;
                LDSM4(bh0,bh1,bh2,bh3, wHb + boff);
                LDSM4(bl0,bl1,bl2,bl3, wLb + boff);
                MMA16816(dacc[2*np][0],dacc[2*np][1],dacc[2*np][2],dacc[2*np][3],
                         ah0,ah1,ah2,ah3, bh0,bh1);
                MMA16816(dacc[2*np][0],dacc[2*np][1],dacc[2*np][2],dacc[2*np][3],
                         al0,al1,al2,al3, bh0,bh1);
                MMA16816(dacc[2*np][0],dacc[2*np][1],dacc[2*np][2],dacc[2*np][3],
                         ah0,ah1,ah2,ah3, bl0,bl1);
                MMA16816(dacc[2*np+1][0],dacc[2*np+1][1],dacc[2*np+1][2],dacc[2*np+1][3],
                         ah0,ah1,ah2,ah3, bh2,bh3);
                MMA16816(dacc[2*np+1][0],dacc[2*np+1][1],dacc[2*np+1][2],dacc[2*np+1][3],
                         al0,al1,al2,al3, bh2,bh3);
                MMA16816(dacc[2*np+1][0],dacc[2*np+1][1],dacc[2*np+1][2],dacc[2*np+1][3],
                         ah0,ah1,ah2,ah3, bl2,bl3);
            }
        }
    }

    // epilogue: +bias, store y, fused BN stats
    __syncthreads();
    if (tid < 128) psm[tid] = 0.f;
    __syncthreads();

    int px = p0 + wid*16 + g;
    float ss[8], sh[8], qs[8], qh[8];
    #pragma unroll
    for (int nt = 0; nt < 8; nt++) {
        int o = nt*8 + 2*tc;
        float b0 = bias[o], b1 = bias[o+1];
        float v00 = dacc[nt][0] + b0, v01 = dacc[nt][1] + b1;
        float v10 = dacc[nt][2] + b0, v11 = dacc[nt][3] + b1;
        *(float2*)&g_y[(size_t)px*64 + o]     = make_float2(v00, v01);
        *(float2*)&g_y[(size_t)(px+8)*64 + o] = make_float2(v10, v11);
        ss[nt] = v00 + v10;        sh[nt] = v01 + v11;
        qs[nt] = v00*v00 + v10*v10; qh[nt] = v01*v01 + v11*v11;
    }
    #pragma unroll
    for (int d = 4; d < 32; d <<= 1) {
        #pragma unroll
        for (int nt = 0; nt < 8; nt++) {
            ss[nt] += __shfl_xor_sync(0xffffffffu, ss[nt], d);
            sh[nt] += __shfl_xor_sync(0xffffffffu, sh[nt], d);
            qs[nt] += __shfl_xor_sync(0xffffffffu, qs[nt], d);
            qh[nt] += __shfl_xor_sync(0xffffffffu, qh[nt], d);
        }
    }
    if (lane < 4) {
        #pragma unroll
        for (int nt = 0; nt < 8; nt++) {
            int o = nt*8 + 2*tc;
            atomicAdd(&psm[o],       ss[nt]);
            atomicAdd(&psm[o+1],     sh[nt]);
            atomicAdd(&psm[64+o],    qs[nt]);
            atomicAdd(&psm[64+o+1],  qh[nt]);
        }
    }
    __syncthreads();
    if (tid < 64) {
        atomicAdd(&g_sum[tid], psm[tid]);
        atomicAdd(&g_sq [tid], psm[64+tid]);
    }
}

// ---------------------------------------------------------------------------
__global__ __launch_bounds__(1024) void k_norm_out(
    const float* __restrict__ gamma, const float* __restrict__ beta,
    float* __restrict__ out)
{
    __shared__ float t[32][33];
    int w0 = blockIdx.x * 32, c0 = blockIdx.y * 32;
    int bh = blockIdx.z;
    int b = bh / Hn, h = bh % Hn;
    int tx = threadIdx.x, ty = threadIdx.y;

    int c = c0 + tx;
    const float inv = 1.0f / (float)PIX;
    float mean = g_sum[c] * inv;
    float var  = g_sq[c] * inv - mean*mean;
    float rstd = rsqrtf(var + 1e-5f);
    float sc = gamma[c] * rstd;
    float sh = beta[c] - mean * sc;

    float v = g_y[((size_t)bh*Wn + (w0+ty))*Cn + c];
    t[ty][tx] = fmaxf(v*sc + sh, 0.f);
    __syncthreads();
    out[(((size_t)b*Cn + (c0+ty))*Hn + h)*Wn + (w0+tx)] = t[tx][ty];
}

// ---------------------------------------------------------------------------
extern "C" void kernel_launch(void* const* d_in, const int* in_sizes, int n_in,
                              void* d_out, int out_size)
{
    const float* x     = (const float*)d_in[0];
    const float* off_w = (const float*)d_in[1];
    const float* off_b = (const float*)d_in[2];
    const float* mod_w = (const float*)d_in[3];
    const float* mod_b = (const float*)d_in[4];
    const float* wmat  = (const float*)d_in[5];
    const float* bias  = (const float*)d_in[6];
    const float* gamma = (const float*)d_in[7];
    const float* beta  = (const float*)d_in[8];
    float* out = (float*)d_out;

    static int configured = 0;
    if (!configured) {
        cudaFuncSetAttribute(k_offmask, cudaFuncAttributeMaxDynamicSharedMemorySize, OSM);
        cudaFuncSetAttribute(k_deform,  cudaFuncAttributeMaxDynamicSharedMemorySize, DSM);
        configured = 1;
    }

    dim3 tgrid(Wn/32, Cn/32, Bn*Hn);
    dim3 tblk(32, 32);

    k_zero<<<1, 64>>>();
    k_wprep<<<64, 256>>>(wmat, off_w, mod_w);
    k_transpose_in<<<tgrid, tblk>>>(x);
    k_offmask<<<PIX/128, 256, OSM>>>(off_b, mod_b);
    k_deform <<<PIX/128, 256, DSM>>>(bias);
    k_norm_out<<<tgrid, tblk>>>(gamma, beta, out);
}